// round 6
// baseline (speedup 1.0000x reference)
#include <cuda_runtime.h>
#include <cuda_bf16.h>

#define IH 512
#define IW 512
#define OH 256
#define OW 256
#define NBC 128
#define SEG 32            // output rows per block
#define NSEG (OH / SEG)   // 8
#define NITER (SEG / 2)   // 2 output rows per iteration

struct RS { float s, v, x; };

// One output column per lane (R3 layout), 2 output rows / 4 input rows per
// iteration, prefetched one full iteration ahead -> 4 LDG.64 in flight/warp.
__global__ __launch_bounds__(256)
void conv_softargmax2d_kernel(const float* __restrict__ x,
                              const float* __restrict__ temp,
                              float* __restrict__ out)
{
    const int lane = threadIdx.x & 31;
    const int warp = threadIdx.x >> 5;
    const int bc   = blockIdx.y;
    const int oy0  = blockIdx.x * SEG;
    const int gox  = warp * 32 + lane;          // output column 0..255
    const bool isL0    = (lane == 0);
    const bool hasLeft = (gox > 0);

    const float invT = __fdividef(1.0f, fmaxf(__ldg(temp), 1e-8f));

    const float* __restrict__ xp = x + (size_t)bc * (IH * IW) + 2 * gox;
    float* __restrict__ coordx = out + (size_t)bc * (2 * OH * OW);
    float* __restrict__ coordy = coordx + OH * OW;
    float* __restrict__ resp   = out + (size_t)NBC * (2 * OH * OW)
                                     + (size_t)bc * (OH * OW);

    auto rowsums = [&](float2 v, float xl) -> RS {
        float e1 = __expf(v.x * invT); float p1 = e1 * v.x;
        float e2 = __expf(v.y * invT); float p2 = e2 * v.y;
        float e0 = __shfl_up_sync(0xffffffffu, e2, 1);
        float p0 = __shfl_up_sync(0xffffffffu, p2, 1);
        if (isL0) {
            if (hasLeft) { e0 = __expf(xl * invT); p0 = e0 * xl; }
            else         { e0 = 0.0f;             p0 = 0.0f;    }
        }
        RS r; r.s = e0 + e1 + e2; r.v = p0 + p1 + p2; r.x = e2 - e0;
        return r;
    };

    // ---- prologue: carry sums for input row 2*oy0-1 (zero at image top) ----
    RS r0 = {0.0f, 0.0f, 0.0f};
    const float* p = xp + (size_t)(2 * oy0) * IW;
    if (oy0 > 0) {
        const float* pp = p - IW;
        float2 v = __ldcs((const float2*)pp);
        float xl = (isL0 && hasLeft) ? __ldcs(pp - 1) : 0.0f;
        r0 = rowsums(v, xl);
    }

    // preload first iteration's 4 rows (2oy0 .. 2oy0+3)
    float2 va = __ldcs((const float2*)(p));
    float2 vb = __ldcs((const float2*)(p + IW));
    float2 vc = __ldcs((const float2*)(p + 2 * IW));
    float2 vd = __ldcs((const float2*)(p + 3 * IW));
    float xla = 0.0f, xlb = 0.0f, xlc = 0.0f, xld = 0.0f;
    if (isL0 && hasLeft) {
        xla = __ldcs(p - 1);          xlb = __ldcs(p + IW - 1);
        xlc = __ldcs(p + 2 * IW - 1); xld = __ldcs(p + 3 * IW - 1);
    }

    const float nx = 2.0f / (float)(IW - 1);
    const float ny = 2.0f / (float)(IH - 1);
    const float gxc = 2.0f * (float)gox;
    float gyc = 2.0f * (float)oy0;
    int o = oy0 * OW + gox;

    #pragma unroll 2
    for (int i = 0; i < NITER; ++i) {
        // prefetch next iteration's 4 rows (clamped on last iter; in-bounds)
        const float* pn = p + 4 * IW;
        const float* pc = (i + 1 < NITER) ? pn : p;
        float2 wa = __ldcs((const float2*)(pc));
        float2 wb = __ldcs((const float2*)(pc + IW));
        float2 wc = __ldcs((const float2*)(pc + 2 * IW));
        float2 wd = __ldcs((const float2*)(pc + 3 * IW));
        float yla = 0.0f, ylb = 0.0f, ylc = 0.0f, yld = 0.0f;
        if (isL0 && hasLeft) {
            yla = __ldcs(pc - 1);          ylb = __ldcs(pc + IW - 1);
            ylc = __ldcs(pc + 2 * IW - 1); yld = __ldcs(pc + 3 * IW - 1);
        }

        RS r1 = rowsums(va, xla);
        RS r2 = rowsums(vb, xlb);

        {   // output row oy0 + 2i  (window rows: carry, va, vb)
            float S  = r0.s + r1.s + r2.s;
            float V  = r0.v + r1.v + r2.v;
            float Sx = r0.x + r1.x + r2.x;
            float Sy = r2.s - r0.s;
            float ri = __fdividef(1.0f, S + 1e-12f);
            __stcs(&coordx[o], fmaf(fmaf(Sx, ri, gxc), nx, -1.0f));
            __stcs(&coordy[o], fmaf(fmaf(Sy, ri, gyc), ny, -1.0f));
            __stcs(&resp[o],   V * ri);
        }

        RS r3 = rowsums(vc, xlc);
        RS r4 = rowsums(vd, xld);

        {   // output row oy0 + 2i + 1  (window rows: vb, vc, vd)
            float S  = r2.s + r3.s + r4.s;
            float V  = r2.v + r3.v + r4.v;
            float Sx = r2.x + r3.x + r4.x;
            float Sy = r4.s - r2.s;
            float ri = __fdividef(1.0f, S + 1e-12f);
            __stcs(&coordx[o + OW], fmaf(fmaf(Sx, ri, gxc), nx, -1.0f));
            __stcs(&coordy[o + OW], fmaf(fmaf(Sy, ri, gyc + 2.0f), ny, -1.0f));
            __stcs(&resp[o + OW],   V * ri);
        }

        // roll
        r0 = r4;
        va = wa; vb = wb; vc = wc; vd = wd;
        xla = yla; xlb = ylb; xlc = ylc; xld = yld;
        p = pn; o += 2 * OW; gyc += 4.0f;
    }
}

extern "C" void kernel_launch(void* const* d_in, const int* in_sizes, int n_in,
                              void* d_out, int out_size)
{
    const float* x = (const float*)d_in[0];
    const float* t = (const float*)d_in[1];
    if (n_in >= 2 && in_sizes[0] == 1) { x = (const float*)d_in[1]; t = (const float*)d_in[0]; }

    dim3 block(256);
    dim3 grid(NSEG, NBC);
    conv_softargmax2d_kernel<<<grid, block>>>(x, t, (float*)d_out);
}

// round 8
// speedup vs baseline: 1.1463x; 1.1463x over previous
#include <cuda_runtime.h>
#include <cuda_bf16.h>

#define IH 512
#define IW 512
#define OH 256
#define OW 256
#define NBC 128
#define SEG 16            // output rows per block
#define NSEG (OH / SEG)   // 16
#define CPB 128           // output columns per block
#define NCB (OW / CPB)    // 2

// R3 inner loop, finer-grained blocks for wave balance:
// 128-thread block = 4 warps, each warp one 32-col strip, SEG=16 output rows.
__global__ __launch_bounds__(128)
void conv_softargmax2d_kernel(const float* __restrict__ x,
                              const float* __restrict__ temp,
                              float* __restrict__ out)
{
    const int lane = threadIdx.x & 31;
    const int bc   = blockIdx.z;
    const int oy0  = blockIdx.y * SEG;
    const int gox  = blockIdx.x * CPB + threadIdx.x;   // output column 0..255
    const bool isL0    = (lane == 0);
    const bool hasLeft = (gox > 0);

    const float invT = __fdividef(1.0f, fmaxf(__ldg(temp), 1e-8f));

    const float* __restrict__ xp = x + (size_t)bc * (IH * IW) + 2 * gox;
    float* __restrict__ coordx = out + (size_t)bc * (2 * OH * OW);
    float* __restrict__ coordy = coordx + OH * OW;
    float* __restrict__ resp   = out + (size_t)NBC * (2 * OH * OW)
                                     + (size_t)bc * (OH * OW);

    // horizontal window sums for one input row:
    //   hs = e(-1)+e(0)+e(+1), hv = same with e*x, hx = e(+1)-e(-1)
    auto rowsums = [&](float2 v, float xl, float& hs, float& hv, float& hx) {
        float e1 = __expf(v.x * invT); float p1 = e1 * v.x;
        float e2 = __expf(v.y * invT); float p2 = e2 * v.y;
        float e0 = __shfl_up_sync(0xffffffffu, e2, 1);
        float p0 = __shfl_up_sync(0xffffffffu, p2, 1);
        if (isL0) {
            if (hasLeft) { e0 = __expf(xl * invT); p0 = e0 * xl; }
            else         { e0 = 0.0f;             p0 = 0.0f;    }
        }
        hs = e0 + e1 + e2;
        hv = p0 + p1 + p2;
        hx = e2 - e0;
    };

    // ---- prologue: sums for input row 2*oy0-1 (zero-pad at image top) ----
    float hs0 = 0.0f, hv0 = 0.0f, hx0 = 0.0f;
    const float* p = xp + (size_t)(2 * oy0) * IW;
    if (oy0 > 0) {
        const float* pp = p - IW;
        float2 v = *(const float2*)pp;
        float xl = (isL0 && hasLeft) ? pp[-1] : 0.0f;
        rowsums(v, xl, hs0, hv0, hx0);
    }

    // preload first iteration's two rows
    float2 v1 = *(const float2*)p;
    float2 v2 = *(const float2*)(p + IW);
    float xl1 = 0.0f, xl2 = 0.0f;
    if (isL0 && hasLeft) { xl1 = p[-1]; xl2 = p[IW - 1]; }

    const float nx = 2.0f / (float)(IW - 1);
    const float ny = 2.0f / (float)(IH - 1);
    const float gxc = 2.0f * (float)gox;
    float gyc = 2.0f * (float)oy0;
    int o = oy0 * OW + gox;

    #pragma unroll 4
    for (int i = 0; i < SEG; ++i) {
        // prefetch next iteration's rows (clamped on last iter; in-bounds)
        const float* pn = p + 2 * IW;
        const float* pc = (i + 1 < SEG) ? pn : p;
        float2 w1 = *(const float2*)pc;
        float2 w2 = *(const float2*)(pc + IW);
        float yl1 = 0.0f, yl2 = 0.0f;
        if (isL0 && hasLeft) { yl1 = pc[-1]; yl2 = pc[IW - 1]; }

        float hs1, hv1, hx1, hs2, hv2, hx2;
        rowsums(v1, xl1, hs1, hv1, hx1);
        rowsums(v2, xl2, hs2, hv2, hx2);

        float S  = hs0 + hs1 + hs2;
        float V  = hv0 + hv1 + hv2;
        float Sx = hx0 + hx1 + hx2;
        float Sy = hs2 - hs0;

        float rinv = __fdividef(1.0f, S + 1e-12f);

        coordx[o] = fmaf(fmaf(Sx, rinv, gxc), nx, -1.0f);
        coordy[o] = fmaf(fmaf(Sy, rinv, gyc), ny, -1.0f);
        resp[o]   = V * rinv;

        // roll: this iteration's bottom row becomes next iteration's top
        hs0 = hs2; hv0 = hv2; hx0 = hx2;
        v1 = w1; v2 = w2; xl1 = yl1; xl2 = yl2;
        p = pn; o += OW; gyc += 2.0f;
    }
}

extern "C" void kernel_launch(void* const* d_in, const int* in_sizes, int n_in,
                              void* d_out, int out_size)
{
    const float* x = (const float*)d_in[0];
    const float* t = (const float*)d_in[1];
    if (n_in >= 2 && in_sizes[0] == 1) { x = (const float*)d_in[1]; t = (const float*)d_in[0]; }

    dim3 block(128);
    dim3 grid(NCB, NSEG, NBC);   // 2 x 16 x 128 = 4096 blocks
    conv_softargmax2d_kernel<<<grid, block>>>(x, t, (float*)d_out);
}

// round 9
// speedup vs baseline: 1.1965x; 1.0437x over previous
#include <cuda_runtime.h>
#include <cuda_bf16.h>

#define IH 512
#define IW 512
#define OH 256
#define OW 256
#define NBC 128
#define SEG 8             // output rows per block
#define NSEG (OH / SEG)   // 32

// Each lane owns TWO output columns (2g, 2g+1); loads input cols 4g..4g+3 as
// one float4 per row. 128-thread block covers the full 256-col output width.
// Left tap (col 4g-1) comes from lane-1's .w via shfl; lane0 of each warp
// loads it (the line is L1-hot from the neighboring warp's float4).
struct RS { float sA, vA, xA, sB, vB, xB; };

__global__ __launch_bounds__(128)
void conv_softargmax2d_kernel(const float* __restrict__ x,
                              const float* __restrict__ temp,
                              float* __restrict__ out)
{
    const int g    = threadIdx.x;               // output-pair index 0..127
    const int lane = g & 31;
    const int bc   = blockIdx.y;
    const int oy0  = blockIdx.x * SEG;
    const bool isL0    = (lane == 0);
    const bool hasLeft = (g > 0);

    // k = log2(e) / max(T, eps): one FMUL + one MUFU per exp
    const float k = __fdividef(1.4426950408889634f, fmaxf(__ldg(temp), 1e-8f));

    const float* __restrict__ xp = x + (size_t)bc * (IH * IW) + 4 * g;
    float* __restrict__ coordx = out + (size_t)bc * (2 * OH * OW);
    float* __restrict__ coordy = coordx + OH * OW;
    float* __restrict__ resp   = out + (size_t)NBC * (2 * OH * OW)
                                     + (size_t)bc * (OH * OW);

    // horizontal window sums for one input row, both output columns
    auto rowsums = [&](float4 v, float xl) -> RS {
        float e0 = exp2f(v.x * k); float p0 = e0 * v.x;
        float e1 = exp2f(v.y * k); float p1 = e1 * v.y;
        float e2 = exp2f(v.z * k); float p2 = e2 * v.z;
        float e3 = exp2f(v.w * k); float p3 = e3 * v.w;
        float eL = __shfl_up_sync(0xffffffffu, e3, 1);
        float pL = __shfl_up_sync(0xffffffffu, p3, 1);
        // branchless lane-0 fix (xl is 0 for lanes that never load it)
        float eX = hasLeft ? exp2f(xl * k) : 0.0f;
        float pX = eX * xl;
        if (isL0) { eL = eX; pL = pX; }          // selp, no divergence
        RS r;
        r.sA = eL + e0 + e1;  r.vA = pL + p0 + p1;  r.xA = e1 - eL;
        r.sB = e1 + e2 + e3;  r.vB = p1 + p2 + p3;  r.xB = e3 - e1;
        return r;
    };

    // ---- prologue: carry sums for input row 2*oy0-1 (zero at image top) ----
    RS r0 = {0, 0, 0, 0, 0, 0};
    const float* p = xp + (size_t)(2 * oy0) * IW;
    if (oy0 > 0) {
        const float* pp = p - IW;
        float4 v = *(const float4*)pp;
        float xl = (isL0 && hasLeft) ? pp[-1] : 0.0f;
        r0 = rowsums(v, xl);
    }

    // preload first iteration's two rows
    float4 v1 = *(const float4*)p;
    float4 v2 = *(const float4*)(p + IW);
    float xl1 = 0.0f, xl2 = 0.0f;
    if (isL0 && hasLeft) { xl1 = p[-1]; xl2 = p[IW - 1]; }

    const float nx = 2.0f / (float)(IW - 1);
    const float ny = 2.0f / (float)(IH - 1);
    const float gxA = (float)(4 * g);
    const float gxB = (float)(4 * g + 2);
    float gyc = 2.0f * (float)oy0;
    int o = oy0 * OW + 2 * g;

    #pragma unroll 2
    for (int i = 0; i < SEG; ++i) {
        // prefetch next iteration's rows (clamped on last iter; in-bounds)
        const float* pn = p + 2 * IW;
        const float* pc = (i + 1 < SEG) ? pn : p;
        float4 w1 = *(const float4*)pc;
        float4 w2 = *(const float4*)(pc + IW);
        float yl1 = 0.0f, yl2 = 0.0f;
        if (isL0 && hasLeft) { yl1 = pc[-1]; yl2 = pc[IW - 1]; }

        RS r1 = rowsums(v1, xl1);
        RS r2 = rowsums(v2, xl2);

        float SA  = r0.sA + r1.sA + r2.sA;
        float VA  = r0.vA + r1.vA + r2.vA;
        float SxA = r0.xA + r1.xA + r2.xA;
        float SyA = r2.sA - r0.sA;

        float SB  = r0.sB + r1.sB + r2.sB;
        float VB  = r0.vB + r1.vB + r2.vB;
        float SxB = r0.xB + r1.xB + r2.xB;
        float SyB = r2.sB - r0.sB;

        float riA = __fdividef(1.0f, SA + 1e-12f);
        float riB = __fdividef(1.0f, SB + 1e-12f);

        float2 cx = { fmaf(fmaf(SxA, riA, gxA), nx, -1.0f),
                      fmaf(fmaf(SxB, riB, gxB), nx, -1.0f) };
        float2 cy = { fmaf(fmaf(SyA, riA, gyc), ny, -1.0f),
                      fmaf(fmaf(SyB, riB, gyc), ny, -1.0f) };
        float2 rv = { VA * riA, VB * riB };

        *(float2*)&coordx[o] = cx;
        *(float2*)&coordy[o] = cy;
        *(float2*)&resp[o]   = rv;

        // roll: this iteration's bottom row becomes next iteration's top
        r0 = r2;
        v1 = w1; v2 = w2; xl1 = yl1; xl2 = yl2;
        p = pn; o += OW; gyc += 2.0f;
    }
}

extern "C" void kernel_launch(void* const* d_in, const int* in_sizes, int n_in,
                              void* d_out, int out_size)
{
    const float* x = (const float*)d_in[0];
    const float* t = (const float*)d_in[1];
    if (n_in >= 2 && in_sizes[0] == 1) { x = (const float*)d_in[1]; t = (const float*)d_in[0]; }

    dim3 block(128);
    dim3 grid(NSEG, NBC);   // 32 x 128 = 4096 blocks
    conv_softargmax2d_kernel<<<grid, block>>>(x, t, (float*)d_out);
}